// round 9
// baseline (speedup 1.0000x reference)
#include <cuda_runtime.h>
#include <cuda_bf16.h>
#include <mma.h>
#include <math.h>
#include <stdint.h>

using namespace nvcuda;

// ---------------- static scratch (no allocation allowed) ----------------
#define N_MAX 150016
#define E_MAX 900032

__device__ float g_y[(size_t)N_MAX * 256];   // GEMM output (pre-BN)
__device__ float g_z[(size_t)N_MAX * 32];    // fp32 agg output (layers 1-2 only)
__device__ float g_x[(size_t)N_MAX * 128];   // fc0 output (pre-relu; relu in segmax)
__device__ __nv_bfloat16 g_ah[(size_t)N_MAX * 288];  // A hi (bf16, +ones col, padded)
__device__ __nv_bfloat16 g_al[(size_t)N_MAX * 288];  // A lo
__device__ __nv_bfloat16 g_wt_hi[288 * 256];         // split weights+bias row [Kpad][NTpad]
__device__ __nv_bfloat16 g_wt_lo[288 * 256];
__device__ int   g_deg[N_MAX];
__device__ int   g_cursor[N_MAX];
__device__ int   g_rowptr[N_MAX + 1];
__device__ int   g_csr_src[E_MAX];
__device__ float g_csr_w[E_MAX];
__device__ float g_dinv[N_MAX];
__device__ float g_cs[N_MAX];
__device__ int   g_blocksum[256];
__device__ int   g_blockoff[257];
__device__ float g_sum[256];
__device__ float g_sq[256];
__device__ float g_scale[256];
__device__ float g_shift[256];
__device__ float g_pool[64 * 128];
__device__ int   g_starts[65];

__device__ __forceinline__ void bsplit(float v, __nv_bfloat16& h, __nv_bfloat16& l) {
    h = __float2bfloat16(v);
    l = __float2bfloat16(v - __bfloat162float(h));
}

// ---------------- prep kernels ----------------
__global__ void k_zero(int n) {
    int i = blockIdx.x * blockDim.x + threadIdx.x;
    if (i < n) { g_deg[i] = 0; g_cursor[i] = 0; }
    if (i < 256) { g_sum[i] = 0.f; g_sq[i] = 0.f; }
}

__global__ void k_hist(const int* __restrict__ dst, int e) {
    int i = blockIdx.x * blockDim.x + threadIdx.x;
    if (i < e) atomicAdd(&g_deg[dst[i]], 1);
}

__global__ void k_scan1(int n) {
    __shared__ int sh[1024];
    int t = threadIdx.x;
    int idx = blockIdx.x * 1024 + t;
    int v = (idx < n) ? g_deg[idx] : 0;
    sh[t] = v;
    __syncthreads();
    for (int off = 1; off < 1024; off <<= 1) {
        int add = (t >= off) ? sh[t - off] : 0;
        __syncthreads();
        sh[t] += add;
        __syncthreads();
    }
    if (idx < n) {
        g_rowptr[idx] = sh[t] - v;
        float d = (float)(v + 1);
        float r = rsqrtf(d);
        g_dinv[idx] = r;
        g_cs[idx] = r * r;
    }
    if (t == 1023) g_blocksum[blockIdx.x] = sh[t];
}

__global__ void k_scan2(int nb, int n) {
    __shared__ int sh[256];
    int t = threadIdx.x;
    int v = (t < nb) ? g_blocksum[t] : 0;
    sh[t] = v;
    __syncthreads();
    for (int off = 1; off < 256; off <<= 1) {
        int add = (t >= off) ? sh[t - off] : 0;
        __syncthreads();
        sh[t] += add;
        __syncthreads();
    }
    int total = sh[255];
    if (t < nb) g_blockoff[t] = sh[t] - v;
    if (t == nb) g_blockoff[nb] = total;
    if (t == (n >> 10)) g_rowptr[n] = total - (sh[t] - v);
}

__device__ __forceinline__ int rp(int i) {
    return g_rowptr[i] + g_blockoff[i >> 10];
}

__global__ void k_place(const int* __restrict__ src, const int* __restrict__ dst, int e) {
    int i = blockIdx.x * blockDim.x + threadIdx.x;
    if (i < e) {
        int d = dst[i], s = src[i];
        int p = rp(d) + atomicAdd(&g_cursor[d], 1);
        g_csr_src[p] = s;
        g_csr_w[p] = g_dinv[s] * g_dinv[d];
    }
}

// ---------------- aggregation ----------------
// MODE 0: input = xext (raw pos). MODE 1: input = relu(bn(g_y)).
// OUT 0: write fp32 g_z. OUT 1: write bf16 hi/lo to g_ah/g_al with
//        ones-column at c==din, zero pad to Kpad (bias fold for WMMA).
template<int MODE, int OUT>
__global__ void k_agg(const float* __restrict__ xext, int n, int din, int Kpad) {
    const float* __restrict__ x = (MODE == 0) ? xext : g_y;
    int gt = blockIdx.x * blockDim.x + threadIdx.x;
    int node = gt >> 5;
    int lane = gt & 31;
    if (node >= n) return;
    int c0 = lane, c1 = lane + 32, c2 = lane + 64;
    bool v0 = c0 < din, v1 = c1 < din, v2 = c2 < din;
    float s0 = 1.f, h0 = 0.f, s1 = 1.f, h1 = 0.f, s2 = 1.f, h2 = 0.f;
    if (MODE) {
        if (v0) { s0 = g_scale[c0]; h0 = g_shift[c0]; }
        if (v1) { s1 = g_scale[c1]; h1 = g_shift[c1]; }
        if (v2) { s2 = g_scale[c2]; h2 = g_shift[c2]; }
    }
    int beg = rp(node), end = rp(node + 1);
    float a0 = 0.f, a1 = 0.f, a2 = 0.f;
    for (int p = beg; p < end; p++) {
        int s = g_csr_src[p];
        float w = g_csr_w[p];
        const float* xs = x + (size_t)s * din;
        if (v0) { float v = xs[c0]; if (MODE) v = fmaxf(fmaf(v, s0, h0), 0.f); a0 = fmaf(v, w, a0); }
        if (v1) { float v = xs[c1]; if (MODE) v = fmaxf(fmaf(v, s1, h1), 0.f); a1 = fmaf(v, w, a1); }
        if (v2) { float v = xs[c2]; if (MODE) v = fmaxf(fmaf(v, s2, h2), 0.f); a2 = fmaf(v, w, a2); }
    }
    float cw = g_cs[node];
    const float* xi = x + (size_t)node * din;
    if (v0) { float v = xi[c0]; if (MODE) v = fmaxf(fmaf(v, s0, h0), 0.f); a0 = fmaf(v, cw, a0); }
    if (v1) { float v = xi[c1]; if (MODE) v = fmaxf(fmaf(v, s1, h1), 0.f); a1 = fmaf(v, cw, a1); }
    if (v2) { float v = xi[c2]; if (MODE) v = fmaxf(fmaf(v, s2, h2), 0.f); a2 = fmaf(v, cw, a2); }

    if (OUT == 0) {
        float* zi = g_z + (size_t)node * din;
        if (v0) zi[c0] = a0;
        if (v1) zi[c1] = a1;
        if (v2) zi[c2] = a2;
    } else {
        __nv_bfloat16* zh = g_ah + (size_t)node * Kpad;
        __nv_bfloat16* zl = g_al + (size_t)node * Kpad;
        __nv_bfloat16 h, l;
        if (v0) { bsplit(a0, h, l); zh[c0] = h; zl[c0] = l; }
        if (v1) { bsplit(a1, h, l); zh[c1] = h; zl[c1] = l; }
        if (v2) { bsplit(a2, h, l); zh[c2] = h; zl[c2] = l; }
        for (int c = din + lane; c < Kpad; c += 32) {
            float v = (c == din) ? 1.f : 0.f;
            bsplit(v, h, l);
            zh[c] = h; zl[c] = l;
        }
    }
}

// ---------------- small GEMM (K<=16, NC<=32): thread per row, fused stats ----
template<int K, int NC>
__global__ __launch_bounds__(256) void k_gemm_s(
    const float* __restrict__ Bm, const float* __restrict__ bias, int M)
{
    __shared__ float Ws[K * NC];
    __shared__ float bs[NC];
    int tid = threadIdx.x;
    for (int i = tid; i < K * NC; i += 256) Ws[i] = Bm[i];
    if (tid < NC) bs[tid] = bias[tid];
    __syncthreads();

    int r = blockIdx.x * 256 + tid;
    bool valid = r < M;
    float a[K];
    #pragma unroll
    for (int k = 0; k < K; k++) a[k] = valid ? g_z[(size_t)r * K + k] : 0.f;
    float acc[NC];
    #pragma unroll
    for (int c = 0; c < NC; c++) acc[c] = valid ? bs[c] : 0.f;
    #pragma unroll
    for (int k = 0; k < K; k++)
        #pragma unroll
        for (int c = 0; c < NC; c++) acc[c] = fmaf(a[k], Ws[k * NC + c], acc[c]);

    if (valid) {
        float4* dst = (float4*)(g_y + (size_t)r * NC);
        #pragma unroll
        for (int c = 0; c < NC; c += 4)
            dst[c >> 2] = make_float4(acc[c], acc[c + 1], acc[c + 2], acc[c + 3]);
    }
    float q[NC];
    #pragma unroll
    for (int c = 0; c < NC; c++) q[c] = acc[c] * acc[c];
    #pragma unroll
    for (int off = 16; off; off >>= 1) {
        #pragma unroll
        for (int c = 0; c < NC; c++) {
            acc[c] += __shfl_down_sync(0xffffffffu, acc[c], off);
            q[c]   += __shfl_down_sync(0xffffffffu, q[c], off);
        }
    }
    if ((tid & 31) == 0) {
        #pragma unroll
        for (int c = 0; c < NC; c++) {
            atomicAdd(&g_sum[c], acc[c]);
            atomicAdd(&g_sq[c], q[c]);
        }
    }
}

// ---------------- weight split: W[K][N] fp32 + bias -> [Kpad][NTpad] bf16 ----
__global__ void k_wsplit(const float* __restrict__ W, const float* __restrict__ bias,
                         int K, int N, int NTpad, int Kpad) {
    int i = blockIdx.x * blockDim.x + threadIdx.x;
    if (i >= Kpad * NTpad) return;
    int k = i / NTpad, nn = i % NTpad;
    float v = 0.f;
    if (nn < N) {
        if (k < K) v = W[(size_t)k * N + nn];
        else if (k == K) v = bias[nn];
    }
    __nv_bfloat16 h, l;
    bsplit(v, h, l);
    g_wt_hi[i] = h;
    g_wt_lo[i] = l;
}

// ---------------- fc0 input convert: relu(bn(g_y)) -> g_ah/g_al, Kpad=288 ----
__global__ void k_conv(int n) {
    int c = threadIdx.x;               // 0..287
    int r0 = blockIdx.x * 8;
    float sc = (c < 256) ? g_scale[c] : 0.f;
    float sh = (c < 256) ? g_shift[c] : 0.f;
    for (int rr = 0; rr < 8; rr++) {
        int r = r0 + rr;
        if (r >= n) return;
        float v;
        if (c < 256) v = fmaxf(fmaf(g_y[(size_t)r * 256 + c], sc, sh), 0.f);
        else v = (c == 256) ? 1.f : 0.f;
        __nv_bfloat16 h, l;
        bsplit(v, h, l);
        g_ah[(size_t)r * 288 + c] = h;
        g_al[(size_t)r * 288 + c] = l;
    }
}

// ---------------- WMMA bf16x3 GEMM, double-buffered ----------------
// 128x64 tile, 256 threads (8 warps = 4m x 2n), K chunks of 32.
// A from g_ah/g_al [M][Kpad]; B from g_wt_hi/lo [Kpad][NTpad].
// DST 0: C=g_y + fused BN stats. DST 1: C=g_x, no stats.
template<int DST>
__global__ __launch_bounds__(256) void k_wmma2(int M, int Kpad, int NTpad, int Nc)
{
    __shared__ __align__(16) char smem[49152];   // 2 x 24KB stage; epilogue aliases
    const float* dummy = nullptr; (void)dummy;
    float* __restrict__ C = DST ? g_x : g_y;

    int tid = threadIdx.x;
    int wid = tid >> 5;
    int warp_m = wid & 3;
    int warp_n = wid >> 2;
    int row0 = blockIdx.y * 128;
    int col0 = blockIdx.x * 64;
    int nch = Kpad >> 5;

    // per-thread load coords
    int a_r = tid >> 1, a_mat = tid & 1;                 // A: 128 rows x {hi,lo}, 64B each
    int b_unit = tid >> 2, b_q = tid & 3;                // B: 32 krows x {hi,lo}, 4 x 32B
    int b_krow = b_unit >> 1, b_mat = b_unit & 1;

    const __nv_bfloat16* aSrc = a_mat ? g_al : g_ah;
    const __nv_bfloat16* bSrc = b_mat ? g_wt_lo : g_wt_hi;

    uint4 ra[4], rb[2];
    auto g2r = [&](int k0) {
        const uint4* pa = (const uint4*)(aSrc + (size_t)(row0 + a_r) * Kpad + k0);
        ra[0] = pa[0]; ra[1] = pa[1]; ra[2] = pa[2]; ra[3] = pa[3];
        const uint4* pb = (const uint4*)(bSrc + (size_t)(k0 + b_krow) * NTpad + col0 + b_q * 16);
        rb[0] = pb[0]; rb[1] = pb[1];
    };
    auto r2s = [&](int bsel) {
        char* buf = smem + bsel * 24576;
        uint4* da = (uint4*)(buf + a_mat * 8192 + a_r * 64);
        da[0] = ra[0]; da[1] = ra[1]; da[2] = ra[2]; da[3] = ra[3];
        uint4* db = (uint4*)(buf + 16384 + b_mat * 4096 + b_krow * 128 + b_q * 32);
        db[0] = rb[0]; db[1] = rb[1];
    };

    wmma::fragment<wmma::accumulator, 16, 16, 16, float> acc[2][2];
    #pragma unroll
    for (int mi = 0; mi < 2; mi++)
        #pragma unroll
        for (int ni = 0; ni < 2; ni++) wmma::fill_fragment(acc[mi][ni], 0.f);

    g2r(0);
    r2s(0);
    __syncthreads();

    for (int ch = 0; ch < nch; ch++) {
        bool more = (ch + 1) < nch;
        if (more) g2r((ch + 1) << 5);
        char* buf = smem + (ch & 1) * 24576;
        const __nv_bfloat16* Ah = (const __nv_bfloat16*)(buf);
        const __nv_bfloat16* Al = (const __nv_bfloat16*)(buf + 8192);
        const __nv_bfloat16* Bh = (const __nv_bfloat16*)(buf + 16384);
        const __nv_bfloat16* Bl = (const __nv_bfloat16*)(buf + 20480);
        #pragma unroll
        for (int kk = 0; kk < 32; kk += 16) {
            wmma::fragment<wmma::matrix_a, 16, 16, 16, __nv_bfloat16, wmma::row_major> ah[2], al[2];
            wmma::fragment<wmma::matrix_b, 16, 16, 16, __nv_bfloat16, wmma::row_major> bh[2], bl[2];
            #pragma unroll
            for (int mi = 0; mi < 2; mi++) {
                int r = warp_m * 32 + mi * 16;
                wmma::load_matrix_sync(ah[mi], Ah + r * 32 + kk, 32);
                wmma::load_matrix_sync(al[mi], Al + r * 32 + kk, 32);
            }
            #pragma unroll
            for (int ni = 0; ni < 2; ni++) {
                int c = warp_n * 32 + ni * 16;
                wmma::load_matrix_sync(bh[ni], Bh + kk * 64 + c, 64);
                wmma::load_matrix_sync(bl[ni], Bl + kk * 64 + c, 64);
            }
            #pragma unroll
            for (int mi = 0; mi < 2; mi++)
                #pragma unroll
                for (int ni = 0; ni < 2; ni++) {
                    wmma::mma_sync(acc[mi][ni], ah[mi], bh[ni], acc[mi][ni]);
                    wmma::mma_sync(acc[mi][ni], ah[mi], bl[ni], acc[mi][ni]);
                    wmma::mma_sync(acc[mi][ni], al[mi], bh[ni], acc[mi][ni]);
                }
        }
        if (more) r2s((ch + 1) & 1);
        __syncthreads();
    }

    // epilogue: stage to smem, coalesced guarded store (+ fused stats)
    float* ob = (float*)smem;                    // 128 x 64
    float* red = (float*)(smem + 32768);         // 64 cols x 4 grp x 2
    #pragma unroll
    for (int mi = 0; mi < 2; mi++)
        #pragma unroll
        for (int ni = 0; ni < 2; ni++)
            wmma::store_matrix_sync(ob + (warp_m * 32 + mi * 16) * 64 + warp_n * 32 + ni * 16,
                                    acc[mi][ni], 64, wmma::mem_row_major);
    __syncthreads();

    for (int i = tid; i < 128 * 64; i += 256) {
        int r = i >> 6, c = i & 63;
        int gr = row0 + r, gc = col0 + c;
        if (gr < M && gc < Nc) C[(size_t)gr * Nc + gc] = ob[i];
    }

    if (DST == 0) {
        int c = tid & 63, grp = tid >> 6;
        float s = 0.f, q = 0.f;
        #pragma unroll 8
        for (int i = 0; i < 32; i++) {
            int r = grp * 32 + i;
            if (row0 + r < M) {
                float v = ob[r * 64 + c];
                s += v; q = fmaf(v, v, q);
            }
        }
        red[(c * 4 + grp) * 2] = s;
        red[(c * 4 + grp) * 2 + 1] = q;
        __syncthreads();
        if (tid < 64) {
            float ts = 0.f, tq = 0.f;
            #pragma unroll
            for (int g = 0; g < 4; g++) {
                ts += red[(tid * 4 + g) * 2];
                tq += red[(tid * 4 + g) * 2 + 1];
            }
            int gc = col0 + tid;
            if (gc < Nc) {
                atomicAdd(&g_sum[gc], ts);
                atomicAdd(&g_sq[gc], tq);
            }
        }
    }
}

// ---------------- BN finalize: scale/shift; reset accumulators -------------
__global__ void k_finalize(const float* __restrict__ gamma, const float* __restrict__ beta,
                           int M, int Nc) {
    int c = threadIdx.x;
    if (c < Nc) {
        float inv = 1.f / (float)M;
        float mean = g_sum[c] * inv;
        float var = g_sq[c] * inv - mean * mean;
        float r = rsqrtf(var + 1e-5f);
        float a = gamma[c] * r;
        g_scale[c] = a;
        g_shift[c] = beta[c] - mean * a;
    }
    g_sum[c] = 0.f;
    g_sq[c] = 0.f;
}

// ---------------- pooling & head ----------------
__global__ void k_bounds(const int* __restrict__ batch, int n, int nb) {
    int g = threadIdx.x;
    if (g > nb) return;
    int lo = 0, hi = n;
    while (lo < hi) {
        int mid = (lo + hi) >> 1;
        if (batch[mid] < g) lo = mid + 1; else hi = mid;
    }
    g_starts[g] = lo;
}

// relu applied here (monotone => commutes with max)
__global__ void k_segmax() {
    __shared__ float sh[4][128];
    int g = blockIdx.x, c = threadIdx.x, s = threadIdx.y;
    int beg = g_starts[g], end = g_starts[g + 1];
    float m = -3.4e38f;
    for (int r = beg + s; r < end; r += 4)
        m = fmaxf(m, g_x[(size_t)r * 128 + c]);
    sh[s][c] = m;
    __syncthreads();
    if (s == 0) {
        m = fmaxf(fmaxf(sh[0][c], sh[1][c]), fmaxf(sh[2][c], sh[3][c]));
        g_pool[g * 128 + c] = fmaxf(m, 0.f);
    }
}

__global__ void k_head(const float* __restrict__ W1, const float* __restrict__ b1,
                       const float* __restrict__ W2, const float* __restrict__ b2,
                       const float* __restrict__ W3, const float* __restrict__ b3,
                       float* __restrict__ out) {
    __shared__ float xs[128];
    __shared__ float red[128];
    int g = blockIdx.x, c = threadIdx.x;
    xs[c] = g_pool[g * 128 + c];
    __syncthreads();

    float v = b1[c];
    #pragma unroll 8
    for (int k = 0; k < 128; k++) v = fmaf(xs[k], W1[k * 128 + c], v);
    v = fmaxf(v, 0.f);
    __syncthreads(); xs[c] = v; __syncthreads();

    v = b2[c];
    #pragma unroll 8
    for (int k = 0; k < 128; k++) v = fmaf(xs[k], W2[k * 128 + c], v);
    v = fmaxf(v, 0.f);
    __syncthreads(); xs[c] = v; __syncthreads();

    float v3 = b3[c];
    #pragma unroll 8
    for (int k = 0; k < 128; k++) v3 = fmaf(xs[k], W3[k * 128 + c], v3);

    red[c] = v3 * v3;
    __syncthreads();
    for (int off = 64; off > 0; off >>= 1) {
        if (c < off) red[c] += red[c + off];
        __syncthreads();
    }
    float nrm = fmaxf(sqrtf(red[0]), 1e-12f);
    out[g * 128 + c] = v3 / nrm;
}

// ---------------- host launch: kernel launches ONLY ----------------
extern "C" void kernel_launch(void* const* d_in, const int* in_sizes, int n_in,
                              void* d_out, int out_size) {
    const float* pos = (const float*)d_in[0];
    const int* ei = (const int*)d_in[1];
    const int* batch = (const int*)d_in[2];
    int n = in_sizes[0] / 3;
    int e = in_sizes[1] / 2;
    const int* src = ei;
    const int* dst = ei + e;
    float* out = (float*)d_out;

    const float *W[5], *bb[5], *gg[5], *be[5];
    for (int l = 0; l < 5; l++) {
        W[l]  = (const float*)d_in[3 + 4 * l];
        bb[l] = (const float*)d_in[4 + 4 * l];
        gg[l] = (const float*)d_in[5 + 4 * l];
        be[l] = (const float*)d_in[6 + 4 * l];
    }
    const float* fc0_W = (const float*)d_in[23];
    const float* fc0_b = (const float*)d_in[24];
    const float* fc1_W = (const float*)d_in[25];
    const float* fc1_b = (const float*)d_in[26];
    const float* fc2_W = (const float*)d_in[27];
    const float* fc2_b = (const float*)d_in[28];
    const float* fc3_W = (const float*)d_in[29];
    const float* fc3_b = (const float*)d_in[30];

    // ---- graph preprocessing ----
    k_zero<<<(n + 255) / 256, 256>>>(n);
    k_hist<<<(e + 255) / 256, 256>>>(dst, e);
    int nb = (n + 1023) / 1024;
    k_scan1<<<nb, 1024>>>(n);
    k_scan2<<<1, 256>>>(nb, n);
    k_place<<<(e + 255) / 256, 256>>>(src, dst, e);

    int aggBlocks = (n + 7) / 8;
    int rb128 = (n + 127) / 128;

    // ---- layer 1: 3 -> 16 (fp32 path) ----
    k_agg<0, 0><<<aggBlocks, 256>>>(pos, n, 3, 0);
    k_gemm_s<3, 16><<<(n + 255) / 256, 256>>>(W[0], bb[0], n);
    k_finalize<<<1, 256>>>(gg[0], be[0], n, 16);

    // ---- layer 2: 16 -> 32 (fp32 path) ----
    k_agg<1, 0><<<aggBlocks, 256>>>(nullptr, n, 16, 0);
    k_gemm_s<16, 32><<<(n + 255) / 256, 256>>>(W[1], bb[1], n);
    k_finalize<<<1, 256>>>(gg[1], be[1], n, 32);

    // ---- layer 3: 32 -> 64 (WMMA, Kpad=64, NTpad=64) ----
    k_agg<1, 1><<<aggBlocks, 256>>>(nullptr, n, 32, 64);
    k_wsplit<<<(64 * 64 + 255) / 256, 256>>>(W[2], bb[2], 32, 64, 64, 64);
    k_wmma2<0><<<dim3(1, rb128), 256>>>(n, 64, 64, 64);
    k_finalize<<<1, 256>>>(gg[2], be[2], n, 64);

    // ---- layer 4: 64 -> 94 (WMMA, Kpad=96, NTpad=128) ----
    k_agg<1, 1><<<aggBlocks, 256>>>(nullptr, n, 64, 96);
    k_wsplit<<<(96 * 128 + 255) / 256, 256>>>(W[3], bb[3], 64, 94, 128, 96);
    k_wmma2<0><<<dim3(2, rb128), 256>>>(n, 96, 128, 94);
    k_finalize<<<1, 256>>>(gg[3], be[3], n, 94);

    // ---- layer 5: 94 -> 256 (WMMA, Kpad=96, NTpad=256) ----
    k_agg<1, 1><<<aggBlocks, 256>>>(nullptr, n, 94, 96);
    k_wsplit<<<(96 * 256 + 255) / 256, 256>>>(W[4], bb[4], 94, 256, 256, 96);
    k_wmma2<0><<<dim3(4, rb128), 256>>>(n, 96, 256, 256);
    k_finalize<<<1, 256>>>(gg[4], be[4], n, 256);

    // ---- fc0: relu(bn(g_y)) @ W (256 -> 128), relu deferred to segmax ----
    k_conv<<<(n + 7) / 8, 288>>>(n);
    k_wsplit<<<(288 * 128 + 255) / 256, 256>>>(fc0_W, fc0_b, 256, 128, 128, 288);
    k_wmma2<1><<<dim3(2, rb128), 256>>>(n, 288, 128, 128);

    // ---- segment max pool (+relu) + head MLP + normalize ----
    k_bounds<<<1, 65>>>(batch, n, 64);
    k_segmax<<<64, dim3(128, 4)>>>();
    k_head<<<64, 128>>>(fc1_W, fc1_b, fc2_W, fc2_b, fc3_W, fc3_b, out);
}

// round 10
// speedup vs baseline: 1.2922x; 1.2922x over previous
#include <cuda_runtime.h>
#include <math.h>

// ---------------- static scratch (no allocation allowed) ----------------
#define N_MAX 150016
#define E_MAX 900032

__device__ float g_y[(size_t)N_MAX * 256];   // GEMM output (pre-BN)
__device__ float g_z[(size_t)N_MAX * 96];    // aggregated input features
__device__ float g_x[(size_t)N_MAX * 128];   // fc0 output
__device__ int   g_deg[N_MAX];
__device__ int   g_cursor[N_MAX];
__device__ int   g_rowptr[N_MAX + 1];        // block-local exclusive scan
__device__ int   g_csr_src[E_MAX];
__device__ float g_csr_w[E_MAX];
__device__ float g_dinv[N_MAX];
__device__ float g_cs[N_MAX];
__device__ int   g_blocksum[256];
__device__ int   g_blockoff[257];
__device__ float g_sum[256];
__device__ float g_sq[256];
__device__ float g_scale[256];
__device__ float g_shift[256];
__device__ float g_pool[64 * 128];
__device__ int   g_starts[65];

// ---------------- f32x2 helpers ----------------
__device__ __forceinline__ void fma2(unsigned long long& acc,
                                     unsigned long long a, unsigned long long b) {
    asm("fma.rn.f32x2 %0, %1, %2, %0;" : "+l"(acc) : "l"(a), "l"(b));
}
__device__ __forceinline__ unsigned long long pack2(float lo, float hi) {
    unsigned long long r;
    asm("mov.b64 %0, {%1, %2};" : "=l"(r) : "f"(lo), "f"(hi));
    return r;
}
__device__ __forceinline__ float2 unpack2(unsigned long long v) {
    float2 r;
    asm("mov.b64 {%0, %1}, %2;" : "=f"(r.x), "=f"(r.y) : "l"(v));
    return r;
}

// ---------------- prep kernels ----------------
__global__ void k_zero(int n) {
    int i = blockIdx.x * blockDim.x + threadIdx.x;
    if (i < n) { g_deg[i] = 0; g_cursor[i] = 0; }
    if (i < 256) { g_sum[i] = 0.f; g_sq[i] = 0.f; }
}

__global__ void k_hist(const int* __restrict__ dst, int e) {
    int i = blockIdx.x * blockDim.x + threadIdx.x;
    if (i < e) atomicAdd(&g_deg[dst[i]], 1);
}

__global__ void k_scan1(int n) {
    __shared__ int sh[1024];
    int t = threadIdx.x;
    int idx = blockIdx.x * 1024 + t;
    int v = (idx < n) ? g_deg[idx] : 0;
    sh[t] = v;
    __syncthreads();
    for (int off = 1; off < 1024; off <<= 1) {
        int add = (t >= off) ? sh[t - off] : 0;
        __syncthreads();
        sh[t] += add;
        __syncthreads();
    }
    if (idx < n) {
        g_rowptr[idx] = sh[t] - v;
        float d = (float)(v + 1);
        float r = rsqrtf(d);
        g_dinv[idx] = r;
        g_cs[idx] = r * r;
    }
    if (t == 1023) g_blocksum[blockIdx.x] = sh[t];
}

__global__ void k_scan2(int nb, int n) {
    __shared__ int sh[256];
    int t = threadIdx.x;
    int v = (t < nb) ? g_blocksum[t] : 0;
    sh[t] = v;
    __syncthreads();
    for (int off = 1; off < 256; off <<= 1) {
        int add = (t >= off) ? sh[t - off] : 0;
        __syncthreads();
        sh[t] += add;
        __syncthreads();
    }
    int total = sh[255];
    if (t < nb) g_blockoff[t] = sh[t] - v;
    if (t == nb) g_blockoff[nb] = total;
    if (t == (n >> 10)) g_rowptr[n] = total - (sh[t] - v);
}

__device__ __forceinline__ int rp(int i) {
    return g_rowptr[i] + g_blockoff[i >> 10];
}

__global__ void k_place(const int* __restrict__ src, const int* __restrict__ dst, int e) {
    int i = blockIdx.x * blockDim.x + threadIdx.x;
    if (i < e) {
        int d = dst[i], s = src[i];
        int p = rp(d) + atomicAdd(&g_cursor[d], 1);
        g_csr_src[p] = s;
        g_csr_w[p] = g_dinv[s] * g_dinv[d];
    }
}

// ---------------- aggregation v2: warp/node, coalesced meta, 4-edge MLP ----
// MODE 0: input = xext (raw pos). MODE 1: input = relu(bn(g_y)).
template<int MODE>
__global__ void k_agg(const float* __restrict__ xext, int n, int din) {
    const float* __restrict__ x = (MODE == 0) ? xext : g_y;
    int gt = blockIdx.x * blockDim.x + threadIdx.x;
    int node = gt >> 5;
    int lane = gt & 31;
    if (node >= n) return;
    int c0 = lane, c1 = lane + 32, c2 = lane + 64;
    bool vc0 = c0 < din, vc1 = c1 < din, vc2 = c2 < din;
    float s0 = 1.f, h0 = 0.f, s1 = 1.f, h1 = 0.f, s2 = 1.f, h2 = 0.f;
    if (MODE) {
        if (vc0) { s0 = g_scale[c0]; h0 = g_shift[c0]; }
        if (vc1) { s1 = g_scale[c1]; h1 = g_shift[c1]; }
        if (vc2) { s2 = g_scale[c2]; h2 = g_shift[c2]; }
    }
    int beg = rp(node), end = rp(node + 1);
    float a0 = 0.f, a1 = 0.f, a2 = 0.f;
    for (int base = beg; base < end; base += 32) {
        int p = base + lane;
        int ms = 0; float mw = 0.f;
        if (p < end) { ms = g_csr_src[p]; mw = g_csr_w[p]; }
        int cnt = min(32, end - base);
        int t = 0;
        for (; t + 4 <= cnt; t += 4) {
            int ss[4]; float ww[4];
            #pragma unroll
            for (int u = 0; u < 4; u++) {
                ss[u] = __shfl_sync(0xffffffffu, ms, t + u);
                ww[u] = __shfl_sync(0xffffffffu, mw, t + u);
            }
            float v0[4], v1[4], v2[4];
            #pragma unroll
            for (int u = 0; u < 4; u++) {
                const float* xs = x + (size_t)ss[u] * din;
                if (vc0) v0[u] = xs[c0];
                if (vc1) v1[u] = xs[c1];
                if (vc2) v2[u] = xs[c2];
            }
            #pragma unroll
            for (int u = 0; u < 4; u++) {
                if (vc0) { float v = v0[u]; if (MODE) v = fmaxf(fmaf(v, s0, h0), 0.f); a0 = fmaf(v, ww[u], a0); }
                if (vc1) { float v = v1[u]; if (MODE) v = fmaxf(fmaf(v, s1, h1), 0.f); a1 = fmaf(v, ww[u], a1); }
                if (vc2) { float v = v2[u]; if (MODE) v = fmaxf(fmaf(v, s2, h2), 0.f); a2 = fmaf(v, ww[u], a2); }
            }
        }
        for (; t < cnt; t++) {
            int s = __shfl_sync(0xffffffffu, ms, t);
            float w = __shfl_sync(0xffffffffu, mw, t);
            const float* xs = x + (size_t)s * din;
            if (vc0) { float v = xs[c0]; if (MODE) v = fmaxf(fmaf(v, s0, h0), 0.f); a0 = fmaf(v, w, a0); }
            if (vc1) { float v = xs[c1]; if (MODE) v = fmaxf(fmaf(v, s1, h1), 0.f); a1 = fmaf(v, w, a1); }
            if (vc2) { float v = xs[c2]; if (MODE) v = fmaxf(fmaf(v, s2, h2), 0.f); a2 = fmaf(v, w, a2); }
        }
    }
    float cw = g_cs[node];
    const float* xi = x + (size_t)node * din;
    float* zi = g_z + (size_t)node * din;
    if (vc0) { float v = xi[c0]; if (MODE) v = fmaxf(fmaf(v, s0, h0), 0.f); zi[c0] = fmaf(v, cw, a0); }
    if (vc1) { float v = xi[c1]; if (MODE) v = fmaxf(fmaf(v, s1, h1), 0.f); zi[c1] = fmaf(v, cw, a1); }
    if (vc2) { float v = xi[c2]; if (MODE) v = fmaxf(fmaf(v, s2, h2), 0.f); zi[c2] = fmaf(v, cw, a2); }
}

// ---------------- small GEMM (K<=16, NC<=32): thread per row, fused stats ----
template<int K, int NC>
__global__ __launch_bounds__(256) void k_gemm_s(
    const float* __restrict__ Bm, const float* __restrict__ bias, int M)
{
    __shared__ float Ws[K * NC];
    __shared__ float bs[NC];
    int tid = threadIdx.x;
    for (int i = tid; i < K * NC; i += 256) Ws[i] = Bm[i];
    if (tid < NC) bs[tid] = bias[tid];
    __syncthreads();

    int r = blockIdx.x * 256 + tid;
    bool valid = r < M;
    float a[K];
    #pragma unroll
    for (int k = 0; k < K; k++) a[k] = valid ? g_z[(size_t)r * K + k] : 0.f;
    float acc[NC];
    #pragma unroll
    for (int c = 0; c < NC; c++) acc[c] = valid ? bs[c] : 0.f;
    #pragma unroll
    for (int k = 0; k < K; k++)
        #pragma unroll
        for (int c = 0; c < NC; c++) acc[c] = fmaf(a[k], Ws[k * NC + c], acc[c]);

    if (valid) {
        float4* dst = (float4*)(g_y + (size_t)r * NC);
        #pragma unroll
        for (int c = 0; c < NC; c += 4)
            dst[c >> 2] = make_float4(acc[c], acc[c + 1], acc[c + 2], acc[c + 3]);
    }
    float q[NC];
    #pragma unroll
    for (int c = 0; c < NC; c++) q[c] = acc[c] * acc[c];
    #pragma unroll
    for (int off = 16; off; off >>= 1) {
        #pragma unroll
        for (int c = 0; c < NC; c++) {
            acc[c] += __shfl_down_sync(0xffffffffu, acc[c], off);
            q[c]   += __shfl_down_sync(0xffffffffu, q[c], off);
        }
    }
    if ((tid & 31) == 0) {
        #pragma unroll
        for (int c = 0; c < NC; c++) {
            atomicAdd(&g_sum[c], acc[c]);
            atomicAdd(&g_sq[c], q[c]);
        }
    }
}

// ---------------- f32x2 tiled SGEMM: BLKM x BLKN, 256 threads, 8x8/thread ----
// FC0==0: g_y = g_z @ W + b (fused BN stats).
// FC0==1: g_x = relu( relu(bn(g_y)) @ W + b ), no stats.
template<int BLKM, int BLKN, int FC0>
__global__ __launch_bounds__(256) void k_gemm2(
    const float* __restrict__ Bm, const float* __restrict__ bias,
    int M, int K, int Nc)
{
    constexpr int NTX = BLKN / 8;          // 8 or 16
    constexpr int NTY = 256 / NTX;         // 32 or 16
    constexpr int NLA = BLKM / 16;         // A-load reps per thread
    const float* __restrict__ A = FC0 ? g_y : g_z;
    float* __restrict__ C = FC0 ? g_x : g_y;

    __shared__ __align__(16) float As[16][BLKM + 4];
    __shared__ __align__(16) float Bs[16][BLKN];
    __shared__ float2 red2[NTY][BLKN];
    __shared__ float sbn_s[256], sbn_h[256];

    int tid = threadIdx.x;
    int tx = tid % NTX;
    int tr = tid / NTX;
    int row0 = blockIdx.y * BLKM;
    int col0 = blockIdx.x * BLKN;

    if (FC0) {
        for (int i = tid; i < K; i += 256) { sbn_s[i] = g_scale[i]; sbn_h[i] = g_shift[i]; }
        __syncthreads();
    }

    unsigned long long acc[8][4];
    #pragma unroll
    for (int i = 0; i < 8; i++)
        #pragma unroll
        for (int j = 0; j < 4; j++) acc[i][j] = 0ull;

    int la_k = tid & 15, la_r = tid >> 4;
    int lb_k0 = tid / BLKN, lb_n = tid % BLKN;
    constexpr int LBSTEP = 256 / BLKN;

    for (int k0 = 0; k0 < K; k0 += 16) {
        #pragma unroll
        for (int j = 0; j < NLA; j++) {
            int r = la_r + j * 16;
            int gk = k0 + la_k;
            float v = 0.f;
            if (row0 + r < M && gk < K) {
                v = A[(size_t)(row0 + r) * K + gk];
                if (FC0) v = fmaxf(fmaf(v, sbn_s[gk], sbn_h[gk]), 0.f);
            }
            As[la_k][r] = v;
        }
        #pragma unroll
        for (int kk = lb_k0; kk < 16; kk += LBSTEP) {
            int gk = k0 + kk, c = col0 + lb_n;
            Bs[kk][lb_n] = (gk < K && c < Nc) ? Bm[(size_t)gk * Nc + c] : 0.f;
        }
        __syncthreads();
        #pragma unroll
        for (int kk = 0; kk < 16; kk++) {
            float4 aLo = *(const float4*)&As[kk][tr * 8];
            float4 aHi = *(const float4*)&As[kk][tr * 8 + 4];
            unsigned long long a2[8];
            a2[0] = pack2(aLo.x, aLo.x); a2[1] = pack2(aLo.y, aLo.y);
            a2[2] = pack2(aLo.z, aLo.z); a2[3] = pack2(aLo.w, aLo.w);
            a2[4] = pack2(aHi.x, aHi.x); a2[5] = pack2(aHi.y, aHi.y);
            a2[6] = pack2(aHi.z, aHi.z); a2[7] = pack2(aHi.w, aHi.w);
            unsigned long long b2[4];
            #pragma unroll
            for (int j = 0; j < 4; j++)
                b2[j] = *(const unsigned long long*)&Bs[kk][2 * tx + 2 * NTX * j];
            #pragma unroll
            for (int i = 0; i < 8; i++)
                #pragma unroll
                for (int j = 0; j < 4; j++)
                    fma2(acc[i][j], a2[i], b2[j]);
        }
        __syncthreads();
    }

    #pragma unroll
    for (int j = 0; j < 4; j++) {
        int lc = 2 * tx + 2 * NTX * j;
        int c = col0 + lc;
        float b0 = (c < Nc) ? bias[c] : 0.f;
        float b1 = (c + 1 < Nc) ? bias[c + 1] : 0.f;
        float s0 = 0.f, q0 = 0.f, s1 = 0.f, q1 = 0.f;
        #pragma unroll
        for (int i = 0; i < 8; i++) {
            int r = row0 + tr * 8 + i;
            float2 v = unpack2(acc[i][j]);
            v.x += b0; v.y += b1;
            if (FC0) { v.x = fmaxf(v.x, 0.f); v.y = fmaxf(v.y, 0.f); }
            if (r < M) {
                if (c < Nc)     C[(size_t)r * Nc + c] = v.x;
                if (c + 1 < Nc) C[(size_t)r * Nc + c + 1] = v.y;
                s0 += v.x; q0 = fmaf(v.x, v.x, q0);
                s1 += v.y; q1 = fmaf(v.y, v.y, q1);
            }
        }
        if (!FC0) {
            red2[tr][lc]     = make_float2(s0, q0);
            red2[tr][lc + 1] = make_float2(s1, q1);
        }
    }
    if (!FC0) {
        __syncthreads();
        if (tr == 0) {
            #pragma unroll
            for (int j = 0; j < 4; j++) {
                #pragma unroll
                for (int h = 0; h < 2; h++) {
                    int lc = 2 * tx + 2 * NTX * j + h;
                    float s = 0.f, q = 0.f;
                    for (int u = 0; u < NTY; u++) {
                        float2 t = red2[u][lc];
                        s += t.x; q += t.y;
                    }
                    int c = col0 + lc;
                    if (c < Nc) {
                        atomicAdd(&g_sum[c], s);
                        atomicAdd(&g_sq[c], q);
                    }
                }
            }
        }
    }
}

// ---------------- BN finalize: scale/shift; reset accumulators -------------
__global__ void k_finalize(const float* __restrict__ gamma, const float* __restrict__ beta,
                           int M, int Nc) {
    int c = threadIdx.x;
    if (c < Nc) {
        float inv = 1.f / (float)M;
        float mean = g_sum[c] * inv;
        float var = g_sq[c] * inv - mean * mean;
        float r = rsqrtf(var + 1e-5f);
        float a = gamma[c] * r;
        g_scale[c] = a;
        g_shift[c] = beta[c] - mean * a;
    }
    g_sum[c] = 0.f;
    g_sq[c] = 0.f;
}

// ---------------- pooling & head ----------------
__global__ void k_bounds(const int* __restrict__ batch, int n, int nb) {
    int g = threadIdx.x;
    if (g > nb) return;
    int lo = 0, hi = n;
    while (lo < hi) {
        int mid = (lo + hi) >> 1;
        if (batch[mid] < g) lo = mid + 1; else hi = mid;
    }
    g_starts[g] = lo;
}

__global__ void k_segmax() {   // reads g_x (N x 128)
    __shared__ float sh[4][128];
    int g = blockIdx.x, c = threadIdx.x, s = threadIdx.y;
    int beg = g_starts[g], end = g_starts[g + 1];
    float m = -3.4e38f;
    for (int r = beg + s; r < end; r += 4)
        m = fmaxf(m, g_x[(size_t)r * 128 + c]);
    sh[s][c] = m;
    __syncthreads();
    if (s == 0) {
        m = fmaxf(fmaxf(sh[0][c], sh[1][c]), fmaxf(sh[2][c], sh[3][c]));
        g_pool[g * 128 + c] = m;
    }
}

__global__ void k_head(const float* __restrict__ W1, const float* __restrict__ b1,
                       const float* __restrict__ W2, const float* __restrict__ b2,
                       const float* __restrict__ W3, const float* __restrict__ b3,
                       float* __restrict__ out) {
    __shared__ float xs[128];
    __shared__ float red[128];
    int g = blockIdx.x, c = threadIdx.x;
    xs[c] = g_pool[g * 128 + c];
    __syncthreads();

    float v = b1[c];
    #pragma unroll 8
    for (int k = 0; k < 128; k++) v = fmaf(xs[k], W1[k * 128 + c], v);
    v = fmaxf(v, 0.f);
    __syncthreads(); xs[c] = v; __syncthreads();

    v = b2[c];
    #pragma unroll 8
    for (int k = 0; k < 128; k++) v = fmaf(xs[k], W2[k * 128 + c], v);
    v = fmaxf(v, 0.f);
    __syncthreads(); xs[c] = v; __syncthreads();

    float v3 = b3[c];
    #pragma unroll 8
    for (int k = 0; k < 128; k++) v3 = fmaf(xs[k], W3[k * 128 + c], v3);

    red[c] = v3 * v3;
    __syncthreads();
    for (int off = 64; off > 0; off >>= 1) {
        if (c < off) red[c] += red[c + off];
        __syncthreads();
    }
    float nrm = fmaxf(sqrtf(red[0]), 1e-12f);
    out[g * 128 + c] = v3 / nrm;
}

// ---------------- host launch: kernel launches ONLY ----------------
extern "C" void kernel_launch(void* const* d_in, const int* in_sizes, int n_in,
                              void* d_out, int out_size) {
    const float* pos = (const float*)d_in[0];
    const int* ei = (const int*)d_in[1];
    const int* batch = (const int*)d_in[2];
    int n = in_sizes[0] / 3;
    int e = in_sizes[1] / 2;
    const int* src = ei;
    const int* dst = ei + e;
    float* out = (float*)d_out;

    const float *W[5], *bb[5], *gg[5], *be[5];
    for (int l = 0; l < 5; l++) {
        W[l]  = (const float*)d_in[3 + 4 * l];
        bb[l] = (const float*)d_in[4 + 4 * l];
        gg[l] = (const float*)d_in[5 + 4 * l];
        be[l] = (const float*)d_in[6 + 4 * l];
    }
    const float* fc0_W = (const float*)d_in[23];
    const float* fc0_b = (const float*)d_in[24];
    const float* fc1_W = (const float*)d_in[25];
    const float* fc1_b = (const float*)d_in[26];
    const float* fc2_W = (const float*)d_in[27];
    const float* fc2_b = (const float*)d_in[28];
    const float* fc3_W = (const float*)d_in[29];
    const float* fc3_b = (const float*)d_in[30];

    // ---- graph preprocessing ----
    k_zero<<<(n + 255) / 256, 256>>>(n);
    k_hist<<<(e + 255) / 256, 256>>>(dst, e);
    int nb = (n + 1023) / 1024;
    k_scan1<<<nb, 1024>>>(n);
    k_scan2<<<1, 256>>>(nb, n);
    k_place<<<(e + 255) / 256, 256>>>(src, dst, e);

    int aggBlocks = (n + 7) / 8;
    int rb128 = (n + 127) / 128;
    int rb256 = (n + 255) / 256;

    // ---- layer 1: 3 -> 16 ----
    k_agg<0><<<aggBlocks, 256>>>(pos, n, 3);
    k_gemm_s<3, 16><<<(n + 255) / 256, 256>>>(W[0], bb[0], n);
    k_finalize<<<1, 256>>>(gg[0], be[0], n, 16);

    // ---- layer 2: 16 -> 32 ----
    k_agg<1><<<aggBlocks, 256>>>(nullptr, n, 16);
    k_gemm_s<16, 32><<<(n + 255) / 256, 256>>>(W[1], bb[1], n);
    k_finalize<<<1, 256>>>(gg[1], be[1], n, 32);

    // ---- layer 3: 32 -> 64 ----
    k_agg<1><<<aggBlocks, 256>>>(nullptr, n, 32);
    k_gemm2<256, 64, 0><<<dim3(1, rb256), 256>>>(W[2], bb[2], n, 32, 64);
    k_finalize<<<1, 256>>>(gg[2], be[2], n, 64);

    // ---- layer 4: 64 -> 94 ----
    k_agg<1><<<aggBlocks, 256>>>(nullptr, n, 64);
    k_gemm2<256, 64, 0><<<dim3(2, rb256), 256>>>(W[3], bb[3], n, 64, 94);
    k_finalize<<<1, 256>>>(gg[3], be[3], n, 94);

    // ---- layer 5: 94 -> 256 ----
    k_agg<1><<<aggBlocks, 256>>>(nullptr, n, 94);
    k_gemm2<128, 128, 0><<<dim3(2, rb128), 256>>>(W[4], bb[4], n, 94, 256);
    k_finalize<<<1, 256>>>(gg[4], be[4], n, 256);

    // ---- fc0: relu(bn(g_y)) @ W (256 -> 128) + relu, into g_x ----
    k_gemm2<128, 128, 1><<<dim3(1, rb128), 256>>>(fc0_W, fc0_b, n, 256, 128);

    // ---- segment max pool + head MLP + normalize ----
    k_bounds<<<1, 65>>>(batch, n, 64);
    k_segmax<<<64, dim3(128, 4)>>>();
    k_head<<<64, 128>>>(fc1_W, fc1_b, fc2_W, fc2_b, fc3_W, fc3_b, out);
}

// round 11
// speedup vs baseline: 1.4311x; 1.1074x over previous
#include <cuda_runtime.h>
#include <math.h>

// ---------------- static scratch (no allocation allowed) ----------------
#define N_MAX 150016
#define E_MAX 900032

__device__ float g_y[(size_t)N_MAX * 256];   // GEMM output (pre-BN)
__device__ float g_z[(size_t)N_MAX * 96];    // aggregated input features
__device__ float g_x[(size_t)N_MAX * 128];   // fc0 output
__device__ int   g_deg[N_MAX];
__device__ int   g_cursor[N_MAX];
__device__ int   g_rowptr[N_MAX + 1];        // block-local exclusive scan
__device__ int2  g_csr[E_MAX];               // (src, weight-bits) fused meta
__device__ float g_dinv[N_MAX];
__device__ float g_cs[N_MAX];
__device__ int   g_blocksum[256];
__device__ int   g_blockoff[257];
__device__ float g_sum[256];
__device__ float g_sq[256];
__device__ float g_scale[256];
__device__ float g_shift[256];
__device__ float g_pool[64 * 128];
__device__ int   g_starts[65];

// ---------------- f32x2 helpers ----------------
__device__ __forceinline__ void fma2(unsigned long long& acc,
                                     unsigned long long a, unsigned long long b) {
    asm("fma.rn.f32x2 %0, %1, %2, %0;" : "+l"(acc) : "l"(a), "l"(b));
}
__device__ __forceinline__ unsigned long long pack2(float lo, float hi) {
    unsigned long long r;
    asm("mov.b64 %0, {%1, %2};" : "=l"(r) : "f"(lo), "f"(hi));
    return r;
}
__device__ __forceinline__ float2 unpack2(unsigned long long v) {
    float2 r;
    asm("mov.b64 {%0, %1}, %2;" : "=f"(r.x), "=f"(r.y) : "l"(v));
    return r;
}

// ---------------- prep kernels ----------------
__global__ void k_zero(int n) {
    int i = blockIdx.x * blockDim.x + threadIdx.x;
    if (i < n) { g_deg[i] = 0; g_cursor[i] = 0; }
    if (i < 256) { g_sum[i] = 0.f; g_sq[i] = 0.f; }
}

__global__ void k_hist(const int* __restrict__ dst, int e) {
    int i = blockIdx.x * blockDim.x + threadIdx.x;
    if (i < e) atomicAdd(&g_deg[dst[i]], 1);
}

__global__ void k_scan1(int n) {
    __shared__ int sh[1024];
    int t = threadIdx.x;
    int idx = blockIdx.x * 1024 + t;
    int v = (idx < n) ? g_deg[idx] : 0;
    sh[t] = v;
    __syncthreads();
    for (int off = 1; off < 1024; off <<= 1) {
        int add = (t >= off) ? sh[t - off] : 0;
        __syncthreads();
        sh[t] += add;
        __syncthreads();
    }
    if (idx < n) {
        g_rowptr[idx] = sh[t] - v;
        float d = (float)(v + 1);
        float r = rsqrtf(d);
        g_dinv[idx] = r;
        g_cs[idx] = r * r;
    }
    if (t == 1023) g_blocksum[blockIdx.x] = sh[t];
}

__global__ void k_scan2(int nb, int n) {
    __shared__ int sh[256];
    int t = threadIdx.x;
    int v = (t < nb) ? g_blocksum[t] : 0;
    sh[t] = v;
    __syncthreads();
    for (int off = 1; off < 256; off <<= 1) {
        int add = (t >= off) ? sh[t - off] : 0;
        __syncthreads();
        sh[t] += add;
        __syncthreads();
    }
    int total = sh[255];
    if (t < nb) g_blockoff[t] = sh[t] - v;
    if (t == nb) g_blockoff[nb] = total;
    if (t == (n >> 10)) g_rowptr[n] = total - (sh[t] - v);
}

__device__ __forceinline__ int rp(int i) {
    return g_rowptr[i] + g_blockoff[i >> 10];
}

__global__ void k_place(const int* __restrict__ src, const int* __restrict__ dst, int e) {
    int i = blockIdx.x * blockDim.x + threadIdx.x;
    if (i < e) {
        int d = dst[i], s = src[i];
        int p = rp(d) + atomicAdd(&g_cursor[d], 1);
        float w = g_dinv[s] * g_dinv[d];
        g_csr[p] = make_int2(s, __float_as_int(w));
    }
}

// ---------------- aggregation: warp/node, pipelined fused-meta loads --------
// MODE 0: input = xext (raw pos). MODE 1: input = relu(bn(g_y)).
template<int MODE>
__global__ void k_agg(const float* __restrict__ xext, int n, int din) {
    const float* __restrict__ x = (MODE == 0) ? xext : g_y;
    int gt = blockIdx.x * blockDim.x + threadIdx.x;
    int node = gt >> 5;
    int lane = gt & 31;
    if (node >= n) return;
    int c0 = lane, c1 = lane + 32, c2 = lane + 64;
    bool v0 = c0 < din, v1 = c1 < din, v2 = c2 < din;
    float s0 = 1.f, h0 = 0.f, s1 = 1.f, h1 = 0.f, s2 = 1.f, h2 = 0.f;
    if (MODE) {
        if (v0) { s0 = g_scale[c0]; h0 = g_shift[c0]; }
        if (v1) { s1 = g_scale[c1]; h1 = g_shift[c1]; }
        if (v2) { s2 = g_scale[c2]; h2 = g_shift[c2]; }
    }
    int beg = rp(node), end = rp(node + 1);
    float a0 = 0.f, a1 = 0.f, a2 = 0.f;
    if (beg < end) {
        int2 meta = g_csr[beg];                 // broadcast LDG.64
        #pragma unroll 4
        for (int p = beg; p < end; p++) {
            int s = meta.x;
            float w = __int_as_float(meta.y);
            if (p + 1 < end) meta = g_csr[p + 1];   // prefetch next meta
            const float* xs = x + (size_t)s * din;
            if (v0) { float v = xs[c0]; if (MODE) v = fmaxf(fmaf(v, s0, h0), 0.f); a0 = fmaf(v, w, a0); }
            if (v1) { float v = xs[c1]; if (MODE) v = fmaxf(fmaf(v, s1, h1), 0.f); a1 = fmaf(v, w, a1); }
            if (v2) { float v = xs[c2]; if (MODE) v = fmaxf(fmaf(v, s2, h2), 0.f); a2 = fmaf(v, w, a2); }
        }
    }
    float cw = g_cs[node];
    const float* xi = x + (size_t)node * din;
    float* zi = g_z + (size_t)node * din;
    if (v0) { float v = xi[c0]; if (MODE) v = fmaxf(fmaf(v, s0, h0), 0.f); zi[c0] = fmaf(v, cw, a0); }
    if (v1) { float v = xi[c1]; if (MODE) v = fmaxf(fmaf(v, s1, h1), 0.f); zi[c1] = fmaf(v, cw, a1); }
    if (v2) { float v = xi[c2]; if (MODE) v = fmaxf(fmaf(v, s2, h2), 0.f); zi[c2] = fmaf(v, cw, a2); }
}

// ---------------- small GEMM (K<=16, NC<=32): thread per row, fused stats ----
template<int K, int NC>
__global__ __launch_bounds__(256) void k_gemm_s(
    const float* __restrict__ Bm, const float* __restrict__ bias, int M)
{
    __shared__ float Ws[K * NC];
    __shared__ float bs[NC];
    int tid = threadIdx.x;
    for (int i = tid; i < K * NC; i += 256) Ws[i] = Bm[i];
    if (tid < NC) bs[tid] = bias[tid];
    __syncthreads();

    int r = blockIdx.x * 256 + tid;
    bool valid = r < M;
    float a[K];
    #pragma unroll
    for (int k = 0; k < K; k++) a[k] = valid ? g_z[(size_t)r * K + k] : 0.f;
    float acc[NC];
    #pragma unroll
    for (int c = 0; c < NC; c++) acc[c] = valid ? bs[c] : 0.f;
    #pragma unroll
    for (int k = 0; k < K; k++)
        #pragma unroll
        for (int c = 0; c < NC; c++) acc[c] = fmaf(a[k], Ws[k * NC + c], acc[c]);

    if (valid) {
        float4* dst = (float4*)(g_y + (size_t)r * NC);
        #pragma unroll
        for (int c = 0; c < NC; c += 4)
            dst[c >> 2] = make_float4(acc[c], acc[c + 1], acc[c + 2], acc[c + 3]);
    }
    float q[NC];
    #pragma unroll
    for (int c = 0; c < NC; c++) q[c] = acc[c] * acc[c];
    #pragma unroll
    for (int off = 16; off; off >>= 1) {
        #pragma unroll
        for (int c = 0; c < NC; c++) {
            acc[c] += __shfl_down_sync(0xffffffffu, acc[c], off);
            q[c]   += __shfl_down_sync(0xffffffffu, q[c], off);
        }
    }
    if ((tid & 31) == 0) {
        #pragma unroll
        for (int c = 0; c < NC; c++) {
            atomicAdd(&g_sum[c], acc[c]);
            atomicAdd(&g_sq[c], q[c]);
        }
    }
}

// ---------------- f32x2 tiled SGEMM: BLKM x BLKN, 256 threads, 8x8/thread ----
// FC0==0: g_y = g_z @ W + b (fused BN stats).
// FC0==1: g_x = relu( relu(bn(g_y)) @ W + b ), no stats.
// red2 aliases As/Bs (dead after mainloop) to cut smem.
template<int BLKM, int BLKN, int FC0>
__global__ __launch_bounds__(256) void k_gemm2(
    const float* __restrict__ Bm, const float* __restrict__ bias,
    int M, int K, int Nc)
{
    constexpr int NTX = BLKN / 8;
    constexpr int NTY = 256 / NTX;
    constexpr int NLA = BLKM / 16;
    constexpr int ASZ = 16 * (BLKM + 4) * 4;
    constexpr int BSZ = 16 * BLKN * 4;
    constexpr int RSZ = NTY * BLKN * 8;
    constexpr int SMSZ = (ASZ + BSZ) > RSZ ? (ASZ + BSZ) : RSZ;
    const float* __restrict__ A = FC0 ? g_y : g_z;
    float* __restrict__ C = FC0 ? g_x : g_y;

    __shared__ __align__(16) char smraw[SMSZ];
    float* As = (float*)smraw;                     // [16][BLKM+4]
    float* Bs = (float*)(smraw + ASZ);             // [16][BLKN]
    float2* red2 = (float2*)smraw;                 // [NTY][BLKN] (epilogue alias)
    __shared__ float sbn_s[256], sbn_h[256];

    int tid = threadIdx.x;
    int tx = tid % NTX;
    int tr = tid / NTX;
    int row0 = blockIdx.y * BLKM;
    int col0 = blockIdx.x * BLKN;

    if (FC0) {
        for (int i = tid; i < K; i += 256) { sbn_s[i] = g_scale[i]; sbn_h[i] = g_shift[i]; }
        __syncthreads();
    }

    unsigned long long acc[8][4];
    #pragma unroll
    for (int i = 0; i < 8; i++)
        #pragma unroll
        for (int j = 0; j < 4; j++) acc[i][j] = 0ull;

    int la_k = tid & 15, la_r = tid >> 4;
    int lb_k0 = tid / BLKN, lb_n = tid % BLKN;
    constexpr int LBSTEP = 256 / BLKN;

    for (int k0 = 0; k0 < K; k0 += 16) {
        #pragma unroll
        for (int j = 0; j < NLA; j++) {
            int r = la_r + j * 16;
            int gk = k0 + la_k;
            float v = 0.f;
            if (row0 + r < M && gk < K) {
                v = A[(size_t)(row0 + r) * K + gk];
                if (FC0) v = fmaxf(fmaf(v, sbn_s[gk], sbn_h[gk]), 0.f);
            }
            As[la_k * (BLKM + 4) + r] = v;
        }
        #pragma unroll
        for (int kk = lb_k0; kk < 16; kk += LBSTEP) {
            int gk = k0 + kk, c = col0 + lb_n;
            Bs[kk * BLKN + lb_n] = (gk < K && c < Nc) ? Bm[(size_t)gk * Nc + c] : 0.f;
        }
        __syncthreads();
        #pragma unroll
        for (int kk = 0; kk < 16; kk++) {
            float4 aLo = *(const float4*)&As[kk * (BLKM + 4) + tr * 8];
            float4 aHi = *(const float4*)&As[kk * (BLKM + 4) + tr * 8 + 4];
            unsigned long long a2[8];
            a2[0] = pack2(aLo.x, aLo.x); a2[1] = pack2(aLo.y, aLo.y);
            a2[2] = pack2(aLo.z, aLo.z); a2[3] = pack2(aLo.w, aLo.w);
            a2[4] = pack2(aHi.x, aHi.x); a2[5] = pack2(aHi.y, aHi.y);
            a2[6] = pack2(aHi.z, aHi.z); a2[7] = pack2(aHi.w, aHi.w);
            unsigned long long b2[4];
            #pragma unroll
            for (int j = 0; j < 4; j++)
                b2[j] = *(const unsigned long long*)&Bs[kk * BLKN + 2 * tx + 2 * NTX * j];
            #pragma unroll
            for (int i = 0; i < 8; i++)
                #pragma unroll
                for (int j = 0; j < 4; j++)
                    fma2(acc[i][j], a2[i], b2[j]);
        }
        __syncthreads();
    }

    // epilogue: bias (+relu for fc0), store, fused stats (red2 aliases As/Bs)
    float sacc[4][2];   // per-colpair {sum,sumsq} x {lo,hi}
    #pragma unroll
    for (int j = 0; j < 4; j++) {
        int lc = 2 * tx + 2 * NTX * j;
        int c = col0 + lc;
        float b0 = (c < Nc) ? bias[c] : 0.f;
        float b1 = (c + 1 < Nc) ? bias[c + 1] : 0.f;
        float s0 = 0.f, q0 = 0.f, s1 = 0.f, q1 = 0.f;
        #pragma unroll
        for (int i = 0; i < 8; i++) {
            int r = row0 + tr * 8 + i;
            float2 v = unpack2(acc[i][j]);
            v.x += b0; v.y += b1;
            if (FC0) { v.x = fmaxf(v.x, 0.f); v.y = fmaxf(v.y, 0.f); }
            if (r < M) {
                if (c < Nc)     C[(size_t)r * Nc + c] = v.x;
                if (c + 1 < Nc) C[(size_t)r * Nc + c + 1] = v.y;
                s0 += v.x; q0 = fmaf(v.x, v.x, q0);
                s1 += v.y; q1 = fmaf(v.y, v.y, q1);
            }
        }
        sacc[j][0] = s0; sacc[j][1] = q0;
        // stash second column's partials in registers via red2 later
        if (!FC0) {
            // write both columns below after sync barrier ordering
            red2[tr * BLKN + lc]     = make_float2(s0, q0);
            red2[tr * BLKN + lc + 1] = make_float2(s1, q1);
        }
    }
    (void)sacc;
    if (!FC0) {
        __syncthreads();
        if (tr == 0) {
            #pragma unroll
            for (int j = 0; j < 4; j++) {
                #pragma unroll
                for (int h = 0; h < 2; h++) {
                    int lc = 2 * tx + 2 * NTX * j + h;
                    float s = 0.f, q = 0.f;
                    for (int u = 0; u < NTY; u++) {
                        float2 t = red2[u * BLKN + lc];
                        s += t.x; q += t.y;
                    }
                    int c = col0 + lc;
                    if (c < Nc) {
                        atomicAdd(&g_sum[c], s);
                        atomicAdd(&g_sq[c], q);
                    }
                }
            }
        }
    }
}

// ---------------- BN finalize: scale/shift; reset accumulators -------------
__global__ void k_finalize(const float* __restrict__ gamma, const float* __restrict__ beta,
                           int M, int Nc) {
    int c = threadIdx.x;
    if (c < Nc) {
        float inv = 1.f / (float)M;
        float mean = g_sum[c] * inv;
        float var = g_sq[c] * inv - mean * mean;
        float r = rsqrtf(var + 1e-5f);
        float a = gamma[c] * r;
        g_scale[c] = a;
        g_shift[c] = beta[c] - mean * a;
    }
    g_sum[c] = 0.f;
    g_sq[c] = 0.f;
}

// ---------------- pooling & head ----------------
__global__ void k_bounds(const int* __restrict__ batch, int n, int nb) {
    int g = threadIdx.x;
    if (g > nb) return;
    int lo = 0, hi = n;
    while (lo < hi) {
        int mid = (lo + hi) >> 1;
        if (batch[mid] < g) lo = mid + 1; else hi = mid;
    }
    g_starts[g] = lo;
}

__global__ void k_segmax() {   // reads g_x (N x 128)
    __shared__ float sh[4][128];
    int g = blockIdx.x, c = threadIdx.x, s = threadIdx.y;
    int beg = g_starts[g], end = g_starts[g + 1];
    float m = -3.4e38f;
    for (int r = beg + s; r < end; r += 4)
        m = fmaxf(m, g_x[(size_t)r * 128 + c]);
    sh[s][c] = m;
    __syncthreads();
    if (s == 0) {
        m = fmaxf(fmaxf(sh[0][c], sh[1][c]), fmaxf(sh[2][c], sh[3][c]));
        g_pool[g * 128 + c] = m;
    }
}

__global__ void k_head(const float* __restrict__ W1, const float* __restrict__ b1,
                       const float* __restrict__ W2, const float* __restrict__ b2,
                       const float* __restrict__ W3, const float* __restrict__ b3,
                       float* __restrict__ out) {
    __shared__ float xs[128];
    __shared__ float red[128];
    int g = blockIdx.x, c = threadIdx.x;
    xs[c] = g_pool[g * 128 + c];
    __syncthreads();

    float v = b1[c];
    #pragma unroll 8
    for (int k = 0; k < 128; k++) v = fmaf(xs[k], W1[k * 128 + c], v);
    v = fmaxf(v, 0.f);
    __syncthreads(); xs[c] = v; __syncthreads();

    v = b2[c];
    #pragma unroll 8
    for (int k = 0; k < 128; k++) v = fmaf(xs[k], W2[k * 128 + c], v);
    v = fmaxf(v, 0.f);
    __syncthreads(); xs[c] = v; __syncthreads();

    float v3 = b3[c];
    #pragma unroll 8
    for (int k = 0; k < 128; k++) v3 = fmaf(xs[k], W3[k * 128 + c], v3);

    red[c] = v3 * v3;
    __syncthreads();
    for (int off = 64; off > 0; off >>= 1) {
        if (c < off) red[c] += red[c + off];
        __syncthreads();
    }
    float nrm = fmaxf(sqrtf(red[0]), 1e-12f);
    out[g * 128 + c] = v3 / nrm;
}

// ---------------- host launch: kernel launches ONLY ----------------
extern "C" void kernel_launch(void* const* d_in, const int* in_sizes, int n_in,
                              void* d_out, int out_size) {
    const float* pos = (const float*)d_in[0];
    const int* ei = (const int*)d_in[1];
    const int* batch = (const int*)d_in[2];
    int n = in_sizes[0] / 3;
    int e = in_sizes[1] / 2;
    const int* src = ei;
    const int* dst = ei + e;
    float* out = (float*)d_out;

    const float *W[5], *bb[5], *gg[5], *be[5];
    for (int l = 0; l < 5; l++) {
        W[l]  = (const float*)d_in[3 + 4 * l];
        bb[l] = (const float*)d_in[4 + 4 * l];
        gg[l] = (const float*)d_in[5 + 4 * l];
        be[l] = (const float*)d_in[6 + 4 * l];
    }
    const float* fc0_W = (const float*)d_in[23];
    const float* fc0_b = (const float*)d_in[24];
    const float* fc1_W = (const float*)d_in[25];
    const float* fc1_b = (const float*)d_in[26];
    const float* fc2_W = (const float*)d_in[27];
    const float* fc2_b = (const float*)d_in[28];
    const float* fc3_W = (const float*)d_in[29];
    const float* fc3_b = (const float*)d_in[30];

    // ---- graph preprocessing ----
    k_zero<<<(n + 255) / 256, 256>>>(n);
    k_hist<<<(e + 255) / 256, 256>>>(dst, e);
    int nb = (n + 1023) / 1024;
    k_scan1<<<nb, 1024>>>(n);
    k_scan2<<<1, 256>>>(nb, n);
    k_place<<<(e + 255) / 256, 256>>>(src, dst, e);

    int aggBlocks = (n + 7) / 8;
    int rb128 = (n + 127) / 128;
    int rb256 = (n + 255) / 256;

    // ---- layer 1: 3 -> 16 ----
    k_agg<0><<<aggBlocks, 256>>>(pos, n, 3);
    k_gemm_s<3, 16><<<(n + 255) / 256, 256>>>(W[0], bb[0], n);
    k_finalize<<<1, 256>>>(gg[0], be[0], n, 16);

    // ---- layer 2: 16 -> 32 ----
    k_agg<1><<<aggBlocks, 256>>>(nullptr, n, 16);
    k_gemm_s<16, 32><<<(n + 255) / 256, 256>>>(W[1], bb[1], n);
    k_finalize<<<1, 256>>>(gg[1], be[1], n, 32);

    // ---- layer 3: 32 -> 64 ----
    k_agg<1><<<aggBlocks, 256>>>(nullptr, n, 32);
    k_gemm2<256, 64, 0><<<dim3(1, rb256), 256>>>(W[2], bb[2], n, 32, 64);
    k_finalize<<<1, 256>>>(gg[2], be[2], n, 64);

    // ---- layer 4: 64 -> 94 ----
    k_agg<1><<<aggBlocks, 256>>>(nullptr, n, 64);
    k_gemm2<256, 64, 0><<<dim3(2, rb256), 256>>>(W[3], bb[3], n, 64, 94);
    k_finalize<<<1, 256>>>(gg[3], be[3], n, 94);

    // ---- layer 5: 94 -> 256 ----
    k_agg<1><<<aggBlocks, 256>>>(nullptr, n, 94);
    k_gemm2<128, 128, 0><<<dim3(2, rb128), 256>>>(W[4], bb[4], n, 94, 256);
    k_finalize<<<1, 256>>>(gg[4], be[4], n, 256);

    // ---- fc0: relu(bn(g_y)) @ W (256 -> 128) + relu, into g_x ----
    k_gemm2<128, 128, 1><<<dim3(1, rb128), 256>>>(fc0_W, fc0_b, n, 256, 128);

    // ---- segment max pool + head MLP + normalize ----
    k_bounds<<<1, 65>>>(batch, n, 64);
    k_segmax<<<64, dim3(128, 4)>>>();
    k_head<<<64, 128>>>(fc1_W, fc1_b, fc2_W, fc2_b, fc3_W, fc3_b, out);
}

// round 12
// speedup vs baseline: 1.4633x; 1.0225x over previous
#include <cuda_runtime.h>
#include <math.h>

// ---------------- static scratch (no allocation allowed) ----------------
#define N_MAX 150016
#define E_MAX 900032

__device__ float g_y[(size_t)N_MAX * 256];   // GEMM output (pre-BN)
__device__ float g_z[(size_t)N_MAX * 96];    // aggregated input features
__device__ float g_x[(size_t)N_MAX * 128];   // fc0 output
__device__ int   g_deg[N_MAX];
__device__ int   g_cursor[N_MAX];
__device__ int   g_rowptr[N_MAX + 1];        // block-local exclusive scan
__device__ int2  g_csr[E_MAX];               // (src, weight-bits) fused meta
__device__ float g_dinv[N_MAX];
__device__ float g_cs[N_MAX];
__device__ int   g_blocksum[256];
__device__ int   g_blockoff[257];
__device__ float g_sum[256];
__device__ float g_sq[256];
__device__ float g_scale[256];
__device__ float g_shift[256];
__device__ float g_pool[64 * 128];
__device__ int   g_starts[65];

// ---------------- f32x2 helpers ----------------
__device__ __forceinline__ void fma2(unsigned long long& acc,
                                     unsigned long long a, unsigned long long b) {
    asm("fma.rn.f32x2 %0, %1, %2, %0;" : "+l"(acc) : "l"(a), "l"(b));
}
__device__ __forceinline__ unsigned long long pack2(float lo, float hi) {
    unsigned long long r;
    asm("mov.b64 %0, {%1, %2};" : "=l"(r) : "f"(lo), "f"(hi));
    return r;
}
__device__ __forceinline__ float2 unpack2(unsigned long long v) {
    float2 r;
    asm("mov.b64 {%0, %1}, %2;" : "=f"(r.x), "=f"(r.y) : "l"(v));
    return r;
}

// ---------------- prep kernels ----------------
__global__ void k_zero(int n) {
    int i = blockIdx.x * blockDim.x + threadIdx.x;
    if (i < n) { g_deg[i] = 0; g_cursor[i] = 0; }
    if (i < 256) { g_sum[i] = 0.f; g_sq[i] = 0.f; }
    if (i < 64 * 128) g_pool[i] = 0.f;
}

__global__ void k_hist(const int* __restrict__ dst, int e) {
    int i = blockIdx.x * blockDim.x + threadIdx.x;
    if (i < e) atomicAdd(&g_deg[dst[i]], 1);
}

__global__ void k_scan1(int n) {
    __shared__ int sh[1024];
    int t = threadIdx.x;
    int idx = blockIdx.x * 1024 + t;
    int v = (idx < n) ? g_deg[idx] : 0;
    sh[t] = v;
    __syncthreads();
    for (int off = 1; off < 1024; off <<= 1) {
        int add = (t >= off) ? sh[t - off] : 0;
        __syncthreads();
        sh[t] += add;
        __syncthreads();
    }
    if (idx < n) {
        g_rowptr[idx] = sh[t] - v;
        float d = (float)(v + 1);
        float r = rsqrtf(d);
        g_dinv[idx] = r;
        g_cs[idx] = r * r;
    }
    if (t == 1023) g_blocksum[blockIdx.x] = sh[t];
}

__global__ void k_scan2(int nb, int n) {
    __shared__ int sh[256];
    int t = threadIdx.x;
    int v = (t < nb) ? g_blocksum[t] : 0;
    sh[t] = v;
    __syncthreads();
    for (int off = 1; off < 256; off <<= 1) {
        int add = (t >= off) ? sh[t - off] : 0;
        __syncthreads();
        sh[t] += add;
        __syncthreads();
    }
    int total = sh[255];
    if (t < nb) g_blockoff[t] = sh[t] - v;
    if (t == nb) g_blockoff[nb] = total;
    if (t == (n >> 10)) g_rowptr[n] = total - (sh[t] - v);
}

__device__ __forceinline__ int rp(int i) {
    return g_rowptr[i] + g_blockoff[i >> 10];
}

__global__ void k_place(const int* __restrict__ src, const int* __restrict__ dst, int e) {
    int i = blockIdx.x * blockDim.x + threadIdx.x;
    if (i < e) {
        int d = dst[i], s = src[i];
        int p = rp(d) + atomicAdd(&g_cursor[d], 1);
        float w = g_dinv[s] * g_dinv[d];
        g_csr[p] = make_int2(s, __float_as_int(w));
    }
}

// ---------------- aggregation: warp/node, 2-deep pipelined meta loads -------
// MODE 0: input = xext (raw pos). MODE 1: input = relu(bn(g_y)).
// Prefetch guard uses (0, w=0) sentinel so accumulation stays branch-free.
template<int MODE>
__global__ void k_agg(const float* __restrict__ xext, int n, int din) {
    const float* __restrict__ x = (MODE == 0) ? xext : g_y;
    int gt = blockIdx.x * blockDim.x + threadIdx.x;
    int node = gt >> 5;
    int lane = gt & 31;
    if (node >= n) return;
    int c0 = lane, c1 = lane + 32, c2 = lane + 64;
    bool v0 = c0 < din, v1 = c1 < din, v2 = c2 < din;
    float s0 = 1.f, h0 = 0.f, s1 = 1.f, h1 = 0.f, s2 = 1.f, h2 = 0.f;
    if (MODE) {
        if (v0) { s0 = g_scale[c0]; h0 = g_shift[c0]; }
        if (v1) { s1 = g_scale[c1]; h1 = g_shift[c1]; }
        if (v2) { s2 = g_scale[c2]; h2 = g_shift[c2]; }
    }
    int beg = rp(node), end = rp(node + 1);
    float a0 = 0.f, a1 = 0.f, a2 = 0.f;
    int2 m0 = (beg < end)     ? g_csr[beg]     : make_int2(0, 0);
    int2 m1 = (beg + 1 < end) ? g_csr[beg + 1] : make_int2(0, 0);
    for (int p = beg; p < end; p += 2) {
        int e0 = m0.x; float w0 = __int_as_float(m0.y);
        int e1 = m1.x; float w1 = __int_as_float(m1.y);
        m0 = (p + 2 < end) ? g_csr[p + 2] : make_int2(0, 0);
        m1 = (p + 3 < end) ? g_csr[p + 3] : make_int2(0, 0);
        const float* xa = x + (size_t)e0 * din;
        const float* xb = x + (size_t)e1 * din;
        float p0a = 0.f, p1a = 0.f, p2a = 0.f, p0b = 0.f, p1b = 0.f, p2b = 0.f;
        if (v0) { p0a = xa[c0]; p0b = xb[c0]; }
        if (v1) { p1a = xa[c1]; p1b = xb[c1]; }
        if (v2) { p2a = xa[c2]; p2b = xb[c2]; }
        if (MODE) {
            if (v0) { p0a = fmaxf(fmaf(p0a, s0, h0), 0.f); p0b = fmaxf(fmaf(p0b, s0, h0), 0.f); }
            if (v1) { p1a = fmaxf(fmaf(p1a, s1, h1), 0.f); p1b = fmaxf(fmaf(p1b, s1, h1), 0.f); }
            if (v2) { p2a = fmaxf(fmaf(p2a, s2, h2), 0.f); p2b = fmaxf(fmaf(p2b, s2, h2), 0.f); }
        }
        if (v0) { a0 = fmaf(p0a, w0, a0); a0 = fmaf(p0b, w1, a0); }
        if (v1) { a1 = fmaf(p1a, w0, a1); a1 = fmaf(p1b, w1, a1); }
        if (v2) { a2 = fmaf(p2a, w0, a2); a2 = fmaf(p2b, w1, a2); }
    }
    float cw = g_cs[node];
    const float* xi = x + (size_t)node * din;
    float* zi = g_z + (size_t)node * din;
    if (v0) { float v = xi[c0]; if (MODE) v = fmaxf(fmaf(v, s0, h0), 0.f); zi[c0] = fmaf(v, cw, a0); }
    if (v1) { float v = xi[c1]; if (MODE) v = fmaxf(fmaf(v, s1, h1), 0.f); zi[c1] = fmaf(v, cw, a1); }
    if (v2) { float v = xi[c2]; if (MODE) v = fmaxf(fmaf(v, s2, h2), 0.f); zi[c2] = fmaf(v, cw, a2); }
}

// ---------------- small GEMM (K<=16, NC<=32): thread per row, fused stats ----
template<int K, int NC>
__global__ __launch_bounds__(256) void k_gemm_s(
    const float* __restrict__ Bm, const float* __restrict__ bias, int M)
{
    __shared__ float Ws[K * NC];
    __shared__ float bs[NC];
    int tid = threadIdx.x;
    for (int i = tid; i < K * NC; i += 256) Ws[i] = Bm[i];
    if (tid < NC) bs[tid] = bias[tid];
    __syncthreads();

    int r = blockIdx.x * 256 + tid;
    bool valid = r < M;
    float a[K];
    #pragma unroll
    for (int k = 0; k < K; k++) a[k] = valid ? g_z[(size_t)r * K + k] : 0.f;
    float acc[NC];
    #pragma unroll
    for (int c = 0; c < NC; c++) acc[c] = valid ? bs[c] : 0.f;
    #pragma unroll
    for (int k = 0; k < K; k++)
        #pragma unroll
        for (int c = 0; c < NC; c++) acc[c] = fmaf(a[k], Ws[k * NC + c], acc[c]);

    if (valid) {
        float4* dst = (float4*)(g_y + (size_t)r * NC);
        #pragma unroll
        for (int c = 0; c < NC; c += 4)
            dst[c >> 2] = make_float4(acc[c], acc[c + 1], acc[c + 2], acc[c + 3]);
    }
    float q[NC];
    #pragma unroll
    for (int c = 0; c < NC; c++) q[c] = acc[c] * acc[c];
    #pragma unroll
    for (int off = 16; off; off >>= 1) {
        #pragma unroll
        for (int c = 0; c < NC; c++) {
            acc[c] += __shfl_down_sync(0xffffffffu, acc[c], off);
            q[c]   += __shfl_down_sync(0xffffffffu, q[c], off);
        }
    }
    if ((tid & 31) == 0) {
        #pragma unroll
        for (int c = 0; c < NC; c++) {
            atomicAdd(&g_sum[c], acc[c]);
            atomicAdd(&g_sq[c], q[c]);
        }
    }
}

// ---------------- f32x2 tiled SGEMM: BLKM x BLKN, 256 threads, 8x8/thread ----
// FC0==0: g_y = g_z @ W + b (fused BN stats).
// FC0==1: g_x = relu( relu(bn(g_y)) @ W + b ), no stats.
// red2 aliases As/Bs; occupancy 2 for load-phase overlap.
template<int BLKM, int BLKN, int FC0>
__global__ __launch_bounds__(256, 2) void k_gemm2(
    const float* __restrict__ Bm, const float* __restrict__ bias,
    int M, int K, int Nc)
{
    constexpr int NTX = BLKN / 8;
    constexpr int NTY = 256 / NTX;
    constexpr int NLA = BLKM / 16;
    constexpr int ASZ = 16 * (BLKM + 4) * 4;
    constexpr int BSZ = 16 * BLKN * 4;
    constexpr int RSZ = NTY * BLKN * 8;
    constexpr int SMSZ = (ASZ + BSZ) > RSZ ? (ASZ + BSZ) : RSZ;
    const float* __restrict__ A = FC0 ? g_y : g_z;
    float* __restrict__ C = FC0 ? g_x : g_y;

    __shared__ __align__(16) char smraw[SMSZ];
    float* As = (float*)smraw;                     // [16][BLKM+4]
    float* Bs = (float*)(smraw + ASZ);             // [16][BLKN]
    float2* red2 = (float2*)smraw;                 // [NTY][BLKN] (epilogue alias)
    __shared__ float sbn_s[256], sbn_h[256];

    int tid = threadIdx.x;
    int tx = tid % NTX;
    int tr = tid / NTX;
    int row0 = blockIdx.y * BLKM;
    int col0 = blockIdx.x * BLKN;

    if (FC0) {
        for (int i = tid; i < K; i += 256) { sbn_s[i] = g_scale[i]; sbn_h[i] = g_shift[i]; }
        __syncthreads();
    }

    unsigned long long acc[8][4];
    #pragma unroll
    for (int i = 0; i < 8; i++)
        #pragma unroll
        for (int j = 0; j < 4; j++) acc[i][j] = 0ull;

    int la_k = tid & 15, la_r = tid >> 4;
    int lb_k0 = tid / BLKN, lb_n = tid % BLKN;
    constexpr int LBSTEP = 256 / BLKN;

    for (int k0 = 0; k0 < K; k0 += 16) {
        #pragma unroll
        for (int j = 0; j < NLA; j++) {
            int r = la_r + j * 16;
            int gk = k0 + la_k;
            float v = 0.f;
            if (row0 + r < M && gk < K) {
                v = A[(size_t)(row0 + r) * K + gk];
                if (FC0) v = fmaxf(fmaf(v, sbn_s[gk], sbn_h[gk]), 0.f);
            }
            As[la_k * (BLKM + 4) + r] = v;
        }
        #pragma unroll
        for (int kk = lb_k0; kk < 16; kk += LBSTEP) {
            int gk = k0 + kk, c = col0 + lb_n;
            Bs[kk * BLKN + lb_n] = (gk < K && c < Nc) ? Bm[(size_t)gk * Nc + c] : 0.f;
        }
        __syncthreads();
        #pragma unroll
        for (int kk = 0; kk < 16; kk++) {
            float4 aLo = *(const float4*)&As[kk * (BLKM + 4) + tr * 8];
            float4 aHi = *(const float4*)&As[kk * (BLKM + 4) + tr * 8 + 4];
            unsigned long long a2[8];
            a2[0] = pack2(aLo.x, aLo.x); a2[1] = pack2(aLo.y, aLo.y);
            a2[2] = pack2(aLo.z, aLo.z); a2[3] = pack2(aLo.w, aLo.w);
            a2[4] = pack2(aHi.x, aHi.x); a2[5] = pack2(aHi.y, aHi.y);
            a2[6] = pack2(aHi.z, aHi.z); a2[7] = pack2(aHi.w, aHi.w);
            unsigned long long b2[4];
            #pragma unroll
            for (int j = 0; j < 4; j++)
                b2[j] = *(const unsigned long long*)&Bs[kk * BLKN + 2 * tx + 2 * NTX * j];
            #pragma unroll
            for (int i = 0; i < 8; i++)
                #pragma unroll
                for (int j = 0; j < 4; j++)
                    fma2(acc[i][j], a2[i], b2[j]);
        }
        __syncthreads();
    }

    // epilogue: bias (+relu for fc0), store, fused stats (red2 aliases As/Bs)
    #pragma unroll
    for (int j = 0; j < 4; j++) {
        int lc = 2 * tx + 2 * NTX * j;
        int c = col0 + lc;
        float b0 = (c < Nc) ? bias[c] : 0.f;
        float b1 = (c + 1 < Nc) ? bias[c + 1] : 0.f;
        float s0 = 0.f, q0 = 0.f, s1 = 0.f, q1 = 0.f;
        #pragma unroll
        for (int i = 0; i < 8; i++) {
            int r = row0 + tr * 8 + i;
            float2 v = unpack2(acc[i][j]);
            v.x += b0; v.y += b1;
            if (FC0) { v.x = fmaxf(v.x, 0.f); v.y = fmaxf(v.y, 0.f); }
            if (r < M) {
                if (c < Nc)     C[(size_t)r * Nc + c] = v.x;
                if (c + 1 < Nc) C[(size_t)r * Nc + c + 1] = v.y;
                s0 += v.x; q0 = fmaf(v.x, v.x, q0);
                s1 += v.y; q1 = fmaf(v.y, v.y, q1);
            }
        }
        if (!FC0) {
            red2[tr * BLKN + lc]     = make_float2(s0, q0);
            red2[tr * BLKN + lc + 1] = make_float2(s1, q1);
        }
    }
    if (!FC0) {
        __syncthreads();
        if (tr == 0) {
            #pragma unroll
            for (int j = 0; j < 4; j++) {
                #pragma unroll
                for (int h = 0; h < 2; h++) {
                    int lc = 2 * tx + 2 * NTX * j + h;
                    float s = 0.f, q = 0.f;
                    for (int u = 0; u < NTY; u++) {
                        float2 t = red2[u * BLKN + lc];
                        s += t.x; q += t.y;
                    }
                    int c = col0 + lc;
                    if (c < Nc) {
                        atomicAdd(&g_sum[c], s);
                        atomicAdd(&g_sq[c], q);
                    }
                }
            }
        }
    }
}

// ---------------- BN finalize: scale/shift; reset accumulators -------------
__global__ void k_finalize(const float* __restrict__ gamma, const float* __restrict__ beta,
                           int M, int Nc) {
    int c = threadIdx.x;
    if (c < Nc) {
        float inv = 1.f / (float)M;
        float mean = g_sum[c] * inv;
        float var = g_sq[c] * inv - mean * mean;
        float r = rsqrtf(var + 1e-5f);
        float a = gamma[c] * r;
        g_scale[c] = a;
        g_shift[c] = beta[c] - mean * a;
    }
    g_sum[c] = 0.f;
    g_sq[c] = 0.f;
}

// ---------------- parallel segment max: relu + atomicMax on bits -----------
// relu(max(x)) = max(relu(x)); relu'd floats are bit-monotone vs 0-init pool.
__global__ void k_segmax2(const int* __restrict__ batch, int n) {
    int c = threadIdx.x;               // 128 channels
    int rows_per = (n + gridDim.x - 1) / gridDim.x;
    int r0 = blockIdx.x * rows_per;
    int r1 = min(n, r0 + rows_per);
    if (r0 >= r1) return;
    int g = batch[r0];
    float m = 0.f;
    for (int r = r0; r < r1; r++) {
        int gr = batch[r];
        if (gr != g) {
            atomicMax((int*)&g_pool[g * 128 + c], __float_as_int(m));
            g = gr; m = 0.f;
        }
        m = fmaxf(m, g_x[(size_t)r * 128 + c]);
    }
    atomicMax((int*)&g_pool[g * 128 + c], __float_as_int(m));
}

__global__ void k_head(const float* __restrict__ W1, const float* __restrict__ b1,
                       const float* __restrict__ W2, const float* __restrict__ b2,
                       const float* __restrict__ W3, const float* __restrict__ b3,
                       float* __restrict__ out) {
    __shared__ float xs[128];
    __shared__ float red[128];
    int g = blockIdx.x, c = threadIdx.x;
    xs[c] = g_pool[g * 128 + c];
    __syncthreads();

    float v = b1[c];
    #pragma unroll 8
    for (int k = 0; k < 128; k++) v = fmaf(xs[k], W1[k * 128 + c], v);
    v = fmaxf(v, 0.f);
    __syncthreads(); xs[c] = v; __syncthreads();

    v = b2[c];
    #pragma unroll 8
    for (int k = 0; k < 128; k++) v = fmaf(xs[k], W2[k * 128 + c], v);
    v = fmaxf(v, 0.f);
    __syncthreads(); xs[c] = v; __syncthreads();

    float v3 = b3[c];
    #pragma unroll 8
    for (int k = 0; k < 128; k++) v3 = fmaf(xs[k], W3[k * 128 + c], v3);

    red[c] = v3 * v3;
    __syncthreads();
    for (int off = 64; off > 0; off >>= 1) {
        if (c < off) red[c] += red[c + off];
        __syncthreads();
    }
    float nrm = fmaxf(sqrtf(red[0]), 1e-12f);
    out[g * 128 + c] = v3 / nrm;
}

// ---------------- host launch: kernel launches ONLY ----------------
extern "C" void kernel_launch(void* const* d_in, const int* in_sizes, int n_in,
                              void* d_out, int out_size) {
    const float* pos = (const float*)d_in[0];
    const int* ei = (const int*)d_in[1];
    const int* batch = (const int*)d_in[2];
    int n = in_sizes[0] / 3;
    int e = in_sizes[1] / 2;
    const int* src = ei;
    const int* dst = ei + e;
    float* out = (float*)d_out;

    const float *W[5], *bb[5], *gg[5], *be[5];
    for (int l = 0; l < 5; l++) {
        W[l]  = (const float*)d_in[3 + 4 * l];
        bb[l] = (const float*)d_in[4 + 4 * l];
        gg[l] = (const float*)d_in[5 + 4 * l];
        be[l] = (const float*)d_in[6 + 4 * l];
    }
    const float* fc0_W = (const float*)d_in[23];
    const float* fc0_b = (const float*)d_in[24];
    const float* fc1_W = (const float*)d_in[25];
    const float* fc1_b = (const float*)d_in[26];
    const float* fc2_W = (const float*)d_in[27];
    const float* fc2_b = (const float*)d_in[28];
    const float* fc3_W = (const float*)d_in[29];
    const float* fc3_b = (const float*)d_in[30];

    // ---- graph preprocessing ----
    k_zero<<<(n + 255) / 256, 256>>>(n);
    k_hist<<<(e + 255) / 256, 256>>>(dst, e);
    int nb = (n + 1023) / 1024;
    k_scan1<<<nb, 1024>>>(n);
    k_scan2<<<1, 256>>>(nb, n);
    k_place<<<(e + 255) / 256, 256>>>(src, dst, e);

    int aggBlocks = (n + 7) / 8;
    int rb128 = (n + 127) / 128;
    int rb256 = (n + 255) / 256;

    // ---- layer 1: 3 -> 16 ----
    k_agg<0><<<aggBlocks, 256>>>(pos, n, 3);
    k_gemm_s<3, 16><<<(n + 255) / 256, 256>>>(W[0], bb[0], n);
    k_finalize<<<1, 256>>>(gg[0], be[0], n, 16);

    // ---- layer 2: 16 -> 32 ----
    k_agg<1><<<aggBlocks, 256>>>(nullptr, n, 16);
    k_gemm_s<16, 32><<<(n + 255) / 256, 256>>>(W[1], bb[1], n);
    k_finalize<<<1, 256>>>(gg[1], be[1], n, 32);

    // ---- layer 3: 32 -> 64 ----
    k_agg<1><<<aggBlocks, 256>>>(nullptr, n, 32);
    k_gemm2<256, 64, 0><<<dim3(1, rb256), 256>>>(W[2], bb[2], n, 32, 64);
    k_finalize<<<1, 256>>>(gg[2], be[2], n, 64);

    // ---- layer 4: 64 -> 94 ----
    k_agg<1><<<aggBlocks, 256>>>(nullptr, n, 64);
    k_gemm2<256, 64, 0><<<dim3(2, rb256), 256>>>(W[3], bb[3], n, 64, 94);
    k_finalize<<<1, 256>>>(gg[3], be[3], n, 94);

    // ---- layer 5: 94 -> 256 ----
    k_agg<1><<<aggBlocks, 256>>>(nullptr, n, 94);
    k_gemm2<128, 128, 0><<<dim3(2, rb128), 256>>>(W[4], bb[4], n, 94, 256);
    k_finalize<<<1, 256>>>(gg[4], be[4], n, 256);

    // ---- fc0: relu(bn(g_y)) @ W (256 -> 128) + relu, into g_x ----
    k_gemm2<128, 128, 1><<<dim3(1, rb128), 256>>>(fc0_W, fc0_b, n, 256, 128);

    // ---- parallel segment max pool + head MLP + normalize ----
    k_segmax2<<<1024, 128>>>(batch, n);
    k_head<<<64, 128>>>(fc1_W, fc1_b, fc2_W, fc2_b, fc3_W, fc3_b, out);
}